// round 7
// baseline (speedup 1.0000x reference)
#include <cuda_runtime.h>
#include <cstdint>
#include <math.h>

#define NW 2048
#define TCC 12
#define TSS 4
#define HHd 128
#define Hd  256
#define Gd  512
#define WXD 768

typedef unsigned long long ull;

// ---------------- scratch (device globals; no allocation) ----------------
__device__ float g_X[TCC][NW][64];        // char/syl embeddings, t-major
__device__ float g_P[2][TCC][NW][Gd];     // input projections (gate-permuted layout)
__device__ float g_h2[2][2][NW][HHd];     // [buf][dir] double-buffered h
__device__ float g_c[2][NW][HHd];
__device__ float g_out[TCC][NW][Hd];      // bilstm outputs
__device__ float g_E[TCC][NW][Hd];        // attention energies (pre-tanh)
__device__ float g_score[TCC][NW];
__device__ float g_wordx[NW][WXD];        // [word_emb | char_ctx | syl_ctx]
__device__ float g_PW[2][NW][Gd];         // word LSTM input projections (gate-permuted)
__device__ float g_wout[NW][Hd];
__device__ float g_WhhP[2][Gd][HHd];      // gate-permuted Whh (char/syl)
__device__ float g_WihP[2][Gd][64];       // gate-permuted Wih (char/syl)
__device__ float g_bP[2][Gd];             // gate-permuted (bih+bhh) (char/syl)
__device__ float g_WihWP[2][Gd][WXD];     // gate-permuted word Wih
__device__ float g_bPW[2][Gd];            // gate-permuted word (bih+bhh)

// ---------------- fast math helpers ----------------
__device__ __forceinline__ float tanha(float x){
    float y; asm("tanh.approx.f32 %0, %1;" : "=f"(y) : "f"(x)); return y;
}
__device__ __forceinline__ float sigfast(float x){
    return fmaf(tanha(0.5f*x), 0.5f, 0.5f);
}
__device__ __forceinline__ ull ffma2(ull a, ull b, ull c){
    ull d;
    asm("fma.rn.f32x2 %0, %1, %2, %3;" : "=l"(d) : "l"(a), "l"(b), "l"(c));
    return d;
}
__device__ __forceinline__ ull pack2(float lo, float hi){
    ull d; asm("mov.b64 %0, {%1, %2};" : "=l"(d) : "f"(lo), "f"(hi)); return d;
}
__device__ __forceinline__ void unpack2(ull a, float& lo, float& hi){
    asm("mov.b64 {%0, %1}, %2;" : "=f"(lo), "=f"(hi) : "l"(a));
}
__device__ __forceinline__ float f2sum(ull a){
    float lo, hi; unpack2(a, lo, hi); return lo + hi;
}

// ---------------- cluster / mbarrier helpers ----------------
__device__ __forceinline__ uint32_t smem_u32(const void* p){
    uint32_t a;
    asm("{ .reg .u64 t; cvta.to.shared.u64 t, %1; cvt.u32.u64 %0, t; }" : "=r"(a) : "l"(p));
    return a;
}
__device__ __forceinline__ uint32_t mapa_u32(uint32_t addr, uint32_t rank){
    uint32_t r;
    asm("mapa.shared::cluster.u32 %0, %1, %2;" : "=r"(r) : "r"(addr), "r"(rank));
    return r;
}
__device__ __forceinline__ void st_remote_f32(uint32_t addr, float v){
    asm volatile("st.shared::cluster.f32 [%0], %1;" :: "r"(addr), "f"(v) : "memory");
}
__device__ __forceinline__ void mbar_init(uint32_t addr, uint32_t count){
    asm volatile("mbarrier.init.shared.b64 [%0], %1;" :: "r"(addr), "r"(count) : "memory");
}
__device__ __forceinline__ void mbar_arrive_remote(uint32_t addr){
    asm volatile("mbarrier.arrive.release.cluster.shared::cluster.b64 _, [%0];" :: "r"(addr) : "memory");
}
__device__ __forceinline__ void mbar_wait_cluster(uint32_t addr, uint32_t parity){
    asm volatile(
        "{\n\t"
        ".reg .pred P;\n\t"
        "WAIT_%=:\n\t"
        "mbarrier.try_wait.parity.acquire.cluster.shared::cta.b64 P, [%0], %1;\n\t"
        "@!P bra WAIT_%=;\n\t"
        "}" :: "r"(addr), "r"(parity) : "memory");
}

// ---------------- gather kernels ----------------
__global__ void k_gatherX(const int* __restrict__ ids, const float* __restrict__ emb, int T){
    int idx = blockIdx.x*256 + threadIdx.x;
    int total = NW*T*64;
    if (idx >= total) return;
    int dcol = idx & 63;
    int r = idx >> 6;              // w*T + t
    int t = r % T, w = r / T;
    g_X[t][w][dcol] = emb[(size_t)ids[r]*64 + dcol];
}

__global__ void k_init(const int* __restrict__ feat, const float* __restrict__ embp){
    int idx = blockIdx.x*256 + threadIdx.x;   // 2*NW*HH = 524288
    int d = idx >> 18;
    int w = (idx >> 7) & (NW-1);
    int j = idx & 127;
    g_h2[0][d][w][j] = embp[(size_t)feat[w]*Hd + d*HHd + j];
    g_c[d][w][j] = 0.f;
}

__global__ void k_gatherW(const int* __restrict__ wid, const float* __restrict__ embw){
    int idx = blockIdx.x*256 + threadIdx.x;   // NW*256
    int w = idx >> 8, j = idx & 255;
    g_wordx[w][j] = embw[(size_t)wid[w]*256 + j];
}

// gate-interleave permutation (char/syl): new row n = 4*j + g  <-  old row g*128 + j
__global__ void k_permW(const float* __restrict__ Wih, const float* __restrict__ Whh,
                        const float* __restrict__ bih, const float* __restrict__ bhh){
    int r = blockIdx.x*256 + threadIdx.x;   // 1024 rows
    if (r >= 1024) return;
    int d = r >> 9, n = r & 511;
    int g = n & 3, j = n >> 2;
    int oldr = g*128 + j;
    const float4* sh_ = (const float4*)(Whh + ((size_t)d*Gd + oldr)*HHd);
    float4* dh = (float4*)&g_WhhP[d][n][0];
    #pragma unroll
    for (int k=0;k<32;k++) dh[k] = sh_[k];
    const float4* si = (const float4*)(Wih + ((size_t)d*Gd + oldr)*64);
    float4* di = (float4*)&g_WihP[d][n][0];
    #pragma unroll
    for (int k=0;k<16;k++) di[k] = si[k];
    g_bP[d][n] = bih[d*Gd + oldr] + bhh[d*Gd + oldr];
}

// gate-interleave permutation for the word-level Wih (768 cols) + bias
__global__ void k_permWord(const float* __restrict__ Wih,
                           const float* __restrict__ bih, const float* __restrict__ bhh){
    int r = blockIdx.x*256 + threadIdx.x;   // 1024 rows
    if (r >= 1024) return;
    int d = r >> 9, n = r & 511;
    int g = n & 3, j = n >> 2;
    int oldr = g*128 + j;
    const float4* s = (const float4*)(Wih + ((size_t)d*Gd + oldr)*WXD);
    float4* dst = (float4*)&g_WihWP[d][n][0];
    #pragma unroll 4
    for (int k=0;k<WXD/4;k++) dst[k] = s[k];
    g_bPW[d][n] = bih[d*Gd + oldr] + bhh[d*Gd + oldr];
}

// ---------------- GEMM: 128x64 block tile, 8x4 per-thread frag, z-batched ----------------
// C = C0 + bias0 + bias1 + A @ B^T.  M%128==0, N%64==0, K%16==0.
__global__ __launch_bounds__(256) void k_gemm(
    const float* __restrict__ A, const float* __restrict__ B,
    const float* __restrict__ bias0, const float* __restrict__ bias1,
    const float* __restrict__ C0, float* __restrict__ C,
    int M, int N, int K,
    long sB, long sBias, long sC0, long sC)
{
    __shared__ __align__(16) float As[2][16][136];
    __shared__ __align__(16) float Bs[2][16][72];
    long z = blockIdx.z;
    B += z*sB;
    if (bias0) bias0 += z*sBias;
    if (bias1) bias1 += z*sBias;
    if (C0) C0 += z*sC0;
    C += z*sC;
    int bn = blockIdx.x*64, bm = blockIdx.y*128;
    int tid = threadIdx.x;
    int tx = tid & 15, ty = tid >> 4;         // n-frag (4), m-frag (8)
    int ar = tid >> 1, ka = (tid & 1) << 3;   // A loader: row 0..127, k 0/8
    int br = tid >> 2, kb = (tid & 3) << 2;   // B loader: row 0..63,  k 0/4/8/12

    const float* Ap = A + (size_t)(bm+ar)*K + ka;
    const float* Bp = B + (size_t)(bn+br)*K + kb;

    {   // prime buffer 0
        float4 a0 = *(const float4*)Ap;
        float4 a1 = *(const float4*)(Ap+4);
        float4 b0 = *(const float4*)Bp;
        #pragma unroll
        for (int j=0;j<4;j++){
            As[0][ka+j][ar]   = (&a0.x)[j];
            As[0][ka+4+j][ar] = (&a1.x)[j];
            Bs[0][kb+j][br]   = (&b0.x)[j];
        }
    }
    __syncthreads();

    ull acc[8][2] = {};
    int buf = 0;
    for (int k0 = 16; ; k0 += 16){
        bool more = (k0 < K);
        float4 na0, na1, nb0;
        if (more){
            na0 = *(const float4*)(Ap + k0);
            na1 = *(const float4*)(Ap + k0 + 4);
            nb0 = *(const float4*)(Bp + k0);
        }
        #pragma unroll
        for (int k=0;k<16;k++){
            float4 av0 = *(const float4*)&As[buf][k][ty<<3];
            float4 av1 = *(const float4*)&As[buf][k][(ty<<3)+4];
            ulonglong2 bv = *(const ulonglong2*)&Bs[buf][k][tx<<2];
            float am[8] = { av0.x,av0.y,av0.z,av0.w, av1.x,av1.y,av1.z,av1.w };
            #pragma unroll
            for (int i=0;i<8;i++){
                ull ai = pack2(am[i], am[i]);
                acc[i][0] = ffma2(ai, bv.x, acc[i][0]);
                acc[i][1] = ffma2(ai, bv.y, acc[i][1]);
            }
        }
        if (!more) break;
        int nb = buf ^ 1;
        #pragma unroll
        for (int j=0;j<4;j++){
            As[nb][ka+j][ar]   = (&na0.x)[j];
            As[nb][ka+4+j][ar] = (&na1.x)[j];
            Bs[nb][kb+j][br]   = (&nb0.x)[j];
        }
        __syncthreads();
        buf = nb;
    }

    int n0 = bn + (tx<<2);
    float bb[4] = {0.f,0.f,0.f,0.f};
    if (bias0){ bb[0]=bias0[n0]; bb[1]=bias0[n0+1]; bb[2]=bias0[n0+2]; bb[3]=bias0[n0+3]; }
    if (bias1){ bb[0]+=bias1[n0]; bb[1]+=bias1[n0+1]; bb[2]+=bias1[n0+2]; bb[3]+=bias1[n0+3]; }
    #pragma unroll
    for (int i=0;i<8;i++){
        int m = bm + (ty<<3) + i;
        float4 v;
        unpack2(acc[i][0], v.x, v.y);
        unpack2(acc[i][1], v.z, v.w);
        v.x += bb[0]; v.y += bb[1]; v.z += bb[2]; v.w += bb[3];
        if (C0){
            float4 c0 = *(const float4*)&C0[(size_t)m*N + n0];
            v.x += c0.x; v.y += c0.y; v.z += c0.z; v.w += c0.w;
        }
        *(float4*)&C[(size_t)m*N + n0] = v;
    }
}

// ---------------- fused recurrence GEMM + LSTM pointwise (gate-permuted, 128x64) ----------------
__global__ __launch_bounds__(256) void k_recfused(int s, int T){
    __shared__ __align__(16) float As[2][16][136];
    __shared__ __align__(16) float Bs[2][16][72];
    int d = blockIdx.z;
    int t = d ? (T-1-s) : s;
    int buf0 = s & 1;
    const float* A  = &g_h2[buf0][d][0][0];   // [NW][128]
    const float* B  = &g_WhhP[d][0][0];       // [512][128]
    const float* C0 = &g_P[d][t][0][0];       // [NW][512]
    int bn = blockIdx.x*64, bm = blockIdx.y*128;
    int tid = threadIdx.x;
    int tx = tid & 15, ty = tid >> 4;
    int ar = tid >> 1, ka = (tid & 1) << 3;
    int br = tid >> 2, kb = (tid & 3) << 2;

    const float* Ap = A + (size_t)(bm+ar)*HHd + ka;
    const float* Bp = B + (size_t)(bn+br)*HHd + kb;

    {
        float4 a0 = *(const float4*)Ap;
        float4 a1 = *(const float4*)(Ap+4);
        float4 b0 = *(const float4*)Bp;
        #pragma unroll
        for (int j=0;j<4;j++){
            As[0][ka+j][ar]   = (&a0.x)[j];
            As[0][ka+4+j][ar] = (&a1.x)[j];
            Bs[0][kb+j][br]   = (&b0.x)[j];
        }
    }
    __syncthreads();

    ull acc[8][2] = {};
    int buf = 0;
    #pragma unroll 2
    for (int k0 = 16; ; k0 += 16){
        bool more = (k0 < HHd);
        float4 na0, na1, nb0;
        if (more){
            na0 = *(const float4*)(Ap + k0);
            na1 = *(const float4*)(Ap + k0 + 4);
            nb0 = *(const float4*)(Bp + k0);
        }
        #pragma unroll
        for (int k=0;k<16;k++){
            float4 av0 = *(const float4*)&As[buf][k][ty<<3];
            float4 av1 = *(const float4*)&As[buf][k][(ty<<3)+4];
            ulonglong2 bv = *(const ulonglong2*)&Bs[buf][k][tx<<2];
            float am[8] = { av0.x,av0.y,av0.z,av0.w, av1.x,av1.y,av1.z,av1.w };
            #pragma unroll
            for (int i=0;i<8;i++){
                ull ai = pack2(am[i], am[i]);
                acc[i][0] = ffma2(ai, bv.x, acc[i][0]);
                acc[i][1] = ffma2(ai, bv.y, acc[i][1]);
            }
        }
        if (!more) break;
        int nb = buf ^ 1;
        #pragma unroll
        for (int j=0;j<4;j++){
            As[nb][ka+j][ar]   = (&na0.x)[j];
            As[nb][ka+4+j][ar] = (&na1.x)[j];
            Bs[nb][kb+j][br]   = (&nb0.x)[j];
        }
        __syncthreads();
        buf = nb;
    }

    int n0 = bn + (tx<<2);
    int j = n0 >> 2;               // columns n0..n0+3 = gates i,f,g,o of hidden unit j
    #pragma unroll
    for (int i=0;i<8;i++){
        int m = bm + (ty<<3) + i;
        float4 p = *(const float4*)&C0[(size_t)m*Gd + n0];
        float gi,gf,gg,go;
        unpack2(acc[i][0], gi, gf);
        unpack2(acc[i][1], gg, go);
        gi += p.x; gf += p.y; gg += p.z; go += p.w;
        float c = sigfast(gf)*g_c[d][m][j] + sigfast(gi)*tanha(gg);
        float h = sigfast(go)*tanha(c);
        g_c[d][m][j] = c;
        g_h2[buf0^1][d][m][j] = h;
        g_out[t][m][d*HHd + j] = h;
    }
}

// ---------------- attention score ----------------
__global__ void k_score(int T, const float* __restrict__ wv){
    int gw = blockIdx.x*8 + (threadIdx.x >> 5);
    int lane = threadIdx.x & 31;
    if (gw >= T*NW) return;
    const float* e = &g_E[0][0][0] + (size_t)gw*Hd;
    float a = 0.f;
    #pragma unroll
    for (int i=0;i<8;i++){
        int g = lane + i*32;
        a += tanha(e[g]) * wv[g];
    }
    #pragma unroll
    for (int o=16;o;o>>=1) a += __shfl_xor_sync(0xffffffffu, a, o);
    if (lane == 0) (&g_score[0][0])[gw] = a;
}

// ---------------- softmax over t + weighted context ----------------
__global__ void k_softctx(int T, int off){
    int w = blockIdx.x, tid = threadIdx.x;    // 256 threads
    __shared__ float sc[TCC];
    if (tid < T) sc[tid] = g_score[tid][w];
    __syncthreads();
    float m = -1e30f;
    for (int t=0;t<T;t++) m = fmaxf(m, sc[t]);
    float den = 0.f, acc = 0.f;
    for (int t=0;t<T;t++){
        float e = expf(sc[t]-m);
        den += e;
        acc += e * g_out[t][w][tid];
    }
    g_wordx[w][off + tid] = acc/den;
}

// ---------------- word-level sequential BiLSTM: 2-CTA cluster per direction ----------------
// grid = 4 blocks, cluster (2,1,1). dir = blockIdx.x>>1, rank = cluster_ctarank.
// Each CTA: 256 threads, 1 gate row each (global permuted row n = rank*256+tid),
// ALL 128 weights in registers (64 ull). Pointwise on threads 0..63 (own 64 hidden
// units); h halves exchanged via st.shared::cluster + remote mbarrier arrive.
__global__ __launch_bounds__(256,1) __cluster_dims__(2,1,1)
void k_wordrec(const float* __restrict__ Whh, const float* __restrict__ PW,
               float* __restrict__ wout)
{
    __shared__ __align__(16) float sh[2][128];   // double-buffered h (full 128)
    __shared__ __align__(16) float scc[64];      // own c
    __shared__ __align__(16) float sg[256];      // own gates
    __shared__ __align__(8)  ull   mbar[2];

    int dir = blockIdx.x >> 1;
    uint32_t rank; asm("mov.u32 %0, %%cluster_ctarank;" : "=r"(rank));
    int tid = threadIdx.x;

    // weight row (gate-permute on the fly): n = rank*256+tid -> oldr = g*128 + j
    int n = (int)rank*256 + tid;
    int g = n & 3, j = n >> 2;
    int oldr = g*HHd + j;
    const float* wrow = Whh + ((size_t)dir*Gd + oldr)*HHd;
    ull w[64];
    {
        const ulonglong2* wp = (const ulonglong2*)wrow;
        #pragma unroll
        for (int i=0;i<32;i++){ ulonglong2 v = wp[i]; w[2*i]=v.x; w[2*i+1]=v.y; }
    }

    uint32_t sh_base = smem_u32(&sh[0][0]);
    uint32_t mb_base = smem_u32(&mbar[0]);
    uint32_t peer = rank ^ 1u;
    uint32_t peer_sh = mapa_u32(sh_base, peer);
    uint32_t peer_mb = mapa_u32(mb_base, peer);

    if (tid == 0){ mbar_init(mb_base, 64); mbar_init(mb_base + 8, 64); }
    if (tid < 128) sh[0][tid] = 0.f;
    if (tid < 64)  scc[tid]   = 0.f;
    __syncthreads();
    asm volatile("barrier.cluster.arrive.aligned;" ::: "memory");
    asm volatile("barrier.cluster.wait.aligned;" ::: "memory");

    const float* PWd = PW + (size_t)dir*NW*Gd + n;
    // prefetch first PW value
    int tfirst = dir ? (NW-1) : 0;
    float pv = __ldg(PWd + (size_t)tfirst*Gd);

    for (int s=0;s<NW;s++){
        int snext = (s+1 < NW) ? s+1 : s;
        int tnext = dir ? (NW-1-snext) : snext;
        float pvn = __ldg(PWd + (size_t)tnext*Gd);   // prefetch next step

        const ulonglong2* hp = (const ulonglong2*)&sh[s&1][0];
        ull a0 = 0ull, a1 = 0ull;
        #pragma unroll
        for (int q=0;q<32;q++){
            ulonglong2 h2 = hp[q];
            a0 = ffma2(w[2*q],   h2.x, a0);
            a1 = ffma2(w[2*q+1], h2.y, a1);
        }
        sg[tid] = pv + f2sum(a0) + f2sum(a1);
        pv = pvn;
        __syncthreads();

        if (tid < 64){
            float4 gv = *(const float4*)&sg[tid<<2];        // i,f,g,o
            float c = sigfast(gv.y)*scc[tid] + sigfast(gv.x)*tanha(gv.z);
            float h = sigfast(gv.w)*tanha(c);
            scc[tid] = c;
            int hidx = (int)rank*64 + tid;
            int nbuf = (s+1)&1;
            int t = dir ? (NW-1-s) : s;
            sh[nbuf][hidx] = h;                              // local half
            st_remote_f32(peer_sh + (uint32_t)((nbuf*128 + hidx)*4), h);  // peer half
            wout[(size_t)t*Hd + dir*HHd + hidx] = h;
            mbar_arrive_remote(peer_mb + (uint32_t)((s&1)*8));
        }
        __syncthreads();
        mbar_wait_cluster(mb_base + (uint32_t)((s&1)*8), (uint32_t)((s>>1)&1));
    }
}

// ---------------- final linear heads + log_softmax ----------------
__global__ void k_head(const float* __restrict__ wout,
                       const float* __restrict__ Wp, const float* __restrict__ bp,
                       const float* __restrict__ Wn, const float* __restrict__ bn_,
                       float* __restrict__ out)
{
    int w = blockIdx.x, tid = threadIdx.x;    // 64 threads
    __shared__ float h[Hd];
    __shared__ float lg[60];
    for (int i=tid;i<Hd;i+=64) h[i] = wout[w*Hd + i];
    __syncthreads();
    if (tid < 47){
        float a = bp[tid];
        const float* r = Wp + (size_t)tid*Hd;
        for (int k=0;k<Hd;k++) a += h[k]*r[k];
        lg[tid] = a;
    } else if (tid < 60){
        int n = tid-47;
        float a = bn_[n];
        const float* r = Wn + (size_t)n*Hd;
        for (int k=0;k<Hd;k++) a += h[k]*r[k];
        lg[tid] = a;
    }
    __syncthreads();
    if (tid < 47){
        float m = -1e30f;
        for (int i=0;i<47;i++) m = fmaxf(m, lg[i]);
        float s = 0.f;
        for (int i=0;i<47;i++) s += expf(lg[i]-m);
        out[(size_t)w*47 + tid] = lg[tid] - m - logf(s);
    } else if (tid < 60){
        float m = -1e30f;
        for (int i=47;i<60;i++) m = fmaxf(m, lg[i]);
        float s = 0.f;
        for (int i=47;i<60;i++) s += expf(lg[i]-m);
        out[(size_t)NW*47 + (size_t)w*13 + (tid-47)] = lg[tid] - m - logf(s);
    }
}

// ---------------- orchestration ----------------
extern "C" void kernel_launch(void* const* d_in, const int* in_sizes, int n_in,
                              void* d_out, int out_size)
{
    const int*   word_seq = (const int*)  d_in[0];
    const int*   syl_seq  = (const int*)  d_in[1];
    const int*   char_seq = (const int*)  d_in[2];
    const int*   feat_seq = (const int*)  d_in[3];
    const float* emb_char = (const float*)d_in[4];
    const float* emb_syl  = (const float*)d_in[5];
    const float* emb_word = (const float*)d_in[6];
    const float* emb_pref = (const float*)d_in[7];
    const float* aW_c = (const float*)d_in[8];
    const float* ab_c = (const float*)d_in[9];
    const float* aw_c = (const float*)d_in[10];
    const float* aW_s = (const float*)d_in[11];
    const float* ab_s = (const float*)d_in[12];
    const float* aw_s = (const float*)d_in[13];
    const float* cWih = (const float*)d_in[14];
    const float* cWhh = (const float*)d_in[15];
    const float* cbih = (const float*)d_in[16];
    const float* cbhh = (const float*)d_in[17];
    const float* sWih = (const float*)d_in[18];
    const float* sWhh = (const float*)d_in[19];
    const float* sbih = (const float*)d_in[20];
    const float* sbhh = (const float*)d_in[21];
    const float* wWih = (const float*)d_in[22];
    const float* wWhh = (const float*)d_in[23];
    const float* wbih = (const float*)d_in[24];
    const float* wbhh = (const float*)d_in[25];
    const float* Wp = (const float*)d_in[26];
    const float* bp = (const float*)d_in[27];
    const float* Wn = (const float*)d_in[28];
    const float* bn = (const float*)d_in[29];
    float* out = (float*)d_out;

    float *pX, *pP, *pE, *pWX, *pPW, *pWout, *pWihP, *pbP, *pOut, *pWihWP, *pbPW;
    cudaGetSymbolAddress((void**)&pX,     g_X);
    cudaGetSymbolAddress((void**)&pP,     g_P);
    cudaGetSymbolAddress((void**)&pE,     g_E);
    cudaGetSymbolAddress((void**)&pWX,    g_wordx);
    cudaGetSymbolAddress((void**)&pPW,    g_PW);
    cudaGetSymbolAddress((void**)&pWout,  g_wout);
    cudaGetSymbolAddress((void**)&pWihP,  g_WihP);
    cudaGetSymbolAddress((void**)&pbP,    g_bP);
    cudaGetSymbolAddress((void**)&pOut,   g_out);
    cudaGetSymbolAddress((void**)&pWihWP, g_WihWP);
    cudaGetSymbolAddress((void**)&pbPW,   g_bPW);

    // ===== char + syl composition phases =====
    for (int phase = 0; phase < 2; phase++){
        int T            = phase == 0 ? TCC      : TSS;
        const int*   ids = phase == 0 ? char_seq : syl_seq;
        const float* emb = phase == 0 ? emb_char : emb_syl;
        const float* Wih = phase == 0 ? cWih : sWih;
        const float* Whh = phase == 0 ? cWhh : sWhh;
        const float* bih = phase == 0 ? cbih : sbih;
        const float* bhh = phase == 0 ? cbhh : sbhh;
        const float* aW  = phase == 0 ? aW_c : aW_s;
        const float* ab  = phase == 0 ? ab_c : ab_s;
        const float* aw  = phase == 0 ? aw_c : aw_s;
        int off          = phase == 0 ? 256 : 512;
        int M            = T * NW;

        k_permW<<<4, 256>>>(Wih, Whh, bih, bhh);
        k_init<<<2048, 256>>>(feat_seq, emb_pref);
        k_gatherX<<<(NW*T*64 + 255)/256, 256>>>(ids, emb, T);

        // input projections, both directions in one launch (permuted layout)
        k_gemm<<<dim3(Gd/64, M/128, 2), 256>>>(
            pX, pWihP, pbP, nullptr, nullptr, pP,
            M, Gd, 64,
            (long)Gd*64, (long)Gd, 0L, (long)TCC*NW*Gd);

        // recurrence: fused GEMM + LSTM update, both directions per launch
        for (int s = 0; s < T; s++)
            k_recfused<<<dim3(Gd/64, NW/128, 2), 256>>>(s, T);

        // attention
        k_gemm<<<dim3(Hd/64, M/128, 1), 256>>>(pOut, aW, ab, nullptr, nullptr, pE,
                                               M, Hd, Hd, 0L, 0L, 0L, 0L);
        k_score<<<(T*NW)/8, 256>>>(T, aw);
        k_softctx<<<NW, 256>>>(T, off);
    }

    // ===== word-level BiLSTM =====
    k_gatherW<<<NW, 256>>>(word_seq, emb_word);
    k_permWord<<<4, 256>>>(wWih, wbih, wbhh);
    k_gemm<<<dim3(Gd/64, NW/128, 2), 256>>>(
        pWX, pWihWP, pbPW, nullptr, nullptr, pPW,
        NW, Gd, WXD,
        (long)Gd*WXD, (long)Gd, 0L, (long)NW*Gd);
    k_wordrec<<<4, 256>>>(wWhh, pPW, pWout);

    // ===== heads =====
    k_head<<<NW, 64>>>(pWout, Wp, bp, Wn, bn, out);
}

// round 8
// speedup vs baseline: 1.2425x; 1.2425x over previous
#include <cuda_runtime.h>
#include <cstdint>
#include <math.h>

#define NW 2048
#define TCC 12
#define TSS 4
#define HHd 128
#define Hd  256
#define Gd  512
#define WXD 768

typedef unsigned long long ull;

// ---------------- scratch (device globals; no allocation) ----------------
__device__ float g_X[TCC][NW][64];        // char/syl embeddings, t-major
__device__ float g_P[2][TCC][NW][Gd];     // input projections (gate-permuted layout)
__device__ float g_h2[2][2][NW][HHd];     // [buf][dir] double-buffered h
__device__ float g_c[2][NW][HHd];
__device__ float g_out[TCC][NW][Hd];      // bilstm outputs
__device__ float g_E[TCC][NW][Hd];        // attention energies (pre-tanh)
__device__ float g_score[TCC][NW];
__device__ float g_wordx[NW][WXD];        // [word_emb | char_ctx | syl_ctx]
__device__ float g_PW[2][NW][Gd];         // word LSTM input projections (natural layout)
__device__ float g_wout[NW][Hd];
__device__ float g_WhhP[2][Gd][HHd];      // gate-permuted Whh (char/syl)
__device__ float g_WihP[2][Gd][64];       // gate-permuted Wih (char/syl)
__device__ float g_bP[2][Gd];             // gate-permuted (bih+bhh) (char/syl)

// ---------------- fast math helpers ----------------
__device__ __forceinline__ float tanha(float x){
    float y; asm("tanh.approx.f32 %0, %1;" : "=f"(y) : "f"(x)); return y;
}
__device__ __forceinline__ float sigfast(float x){
    return fmaf(tanha(0.5f*x), 0.5f, 0.5f);
}
__device__ __forceinline__ ull ffma2(ull a, ull b, ull c){
    ull d;
    asm("fma.rn.f32x2 %0, %1, %2, %3;" : "=l"(d) : "l"(a), "l"(b), "l"(c));
    return d;
}
__device__ __forceinline__ ull pack2(float lo, float hi){
    ull d; asm("mov.b64 %0, {%1, %2};" : "=l"(d) : "f"(lo), "f"(hi)); return d;
}
__device__ __forceinline__ void unpack2(ull a, float& lo, float& hi){
    asm("mov.b64 {%0, %1}, %2;" : "=f"(lo), "=f"(hi) : "l"(a));
}
__device__ __forceinline__ float f2sum(ull a){
    float lo, hi; unpack2(a, lo, hi); return lo + hi;
}
// manual round-to-nearest-even-ish bf16 (unambiguous, no ISA operand-order risk)
__device__ __forceinline__ uint32_t bf16rn(float x){
    uint32_t u = __float_as_uint(x);
    return (u + 0x7fffu + ((u >> 16) & 1u)) >> 16;
}
__device__ __forceinline__ float blo(uint32_t p){ return __uint_as_float(p << 16); }
__device__ __forceinline__ float bhi(uint32_t p){ return __uint_as_float(p & 0xffff0000u); }

// ---------------- gather kernels ----------------
__global__ void k_gatherX(const int* __restrict__ ids, const float* __restrict__ emb, int T){
    int idx = blockIdx.x*256 + threadIdx.x;
    int total = NW*T*64;
    if (idx >= total) return;
    int dcol = idx & 63;
    int r = idx >> 6;              // w*T + t
    int t = r % T, w = r / T;
    g_X[t][w][dcol] = emb[(size_t)ids[r]*64 + dcol];
}

__global__ void k_init(const int* __restrict__ feat, const float* __restrict__ embp){
    int idx = blockIdx.x*256 + threadIdx.x;   // 2*NW*HH = 524288
    int d = idx >> 18;
    int w = (idx >> 7) & (NW-1);
    int j = idx & 127;
    g_h2[0][d][w][j] = embp[(size_t)feat[w]*Hd + d*HHd + j];
    g_c[d][w][j] = 0.f;
}

__global__ void k_gatherW(const int* __restrict__ wid, const float* __restrict__ embw){
    int idx = blockIdx.x*256 + threadIdx.x;   // NW*256
    int w = idx >> 8, j = idx & 255;
    g_wordx[w][j] = embw[(size_t)wid[w]*256 + j];
}

// gate-interleave permutation (char/syl): new row n = 4*j + g  <-  old row g*128 + j
__global__ void k_permW(const float* __restrict__ Wih, const float* __restrict__ Whh,
                        const float* __restrict__ bih, const float* __restrict__ bhh){
    int r = blockIdx.x*256 + threadIdx.x;   // 1024 rows
    if (r >= 1024) return;
    int d = r >> 9, n = r & 511;
    int g = n & 3, j = n >> 2;
    int oldr = g*128 + j;
    const float4* sh_ = (const float4*)(Whh + ((size_t)d*Gd + oldr)*HHd);
    float4* dh = (float4*)&g_WhhP[d][n][0];
    #pragma unroll
    for (int k=0;k<32;k++) dh[k] = sh_[k];
    const float4* si = (const float4*)(Wih + ((size_t)d*Gd + oldr)*64);
    float4* di = (float4*)&g_WihP[d][n][0];
    #pragma unroll
    for (int k=0;k<16;k++) di[k] = si[k];
    g_bP[d][n] = bih[d*Gd + oldr] + bhh[d*Gd + oldr];
}

// ---------------- GEMM: 128x64 block tile, 8x4 per-thread frag, z-batched ----------------
// C = C0 + bias0 + bias1 + A @ B^T.  M%128==0, N%64==0, K%16==0.
__global__ __launch_bounds__(256) void k_gemm(
    const float* __restrict__ A, const float* __restrict__ B,
    const float* __restrict__ bias0, const float* __restrict__ bias1,
    const float* __restrict__ C0, float* __restrict__ C,
    int M, int N, int K,
    long sB, long sBias, long sC0, long sC)
{
    __shared__ __align__(16) float As[2][16][136];
    __shared__ __align__(16) float Bs[2][16][72];
    long z = blockIdx.z;
    B += z*sB;
    if (bias0) bias0 += z*sBias;
    if (bias1) bias1 += z*sBias;
    if (C0) C0 += z*sC0;
    C += z*sC;
    int bn = blockIdx.x*64, bm = blockIdx.y*128;
    int tid = threadIdx.x;
    int tx = tid & 15, ty = tid >> 4;         // n-frag (4), m-frag (8)
    int ar = tid >> 1, ka = (tid & 1) << 3;   // A loader: row 0..127, k 0/8
    int br = tid >> 2, kb = (tid & 3) << 2;   // B loader: row 0..63,  k 0/4/8/12

    const float* Ap = A + (size_t)(bm+ar)*K + ka;
    const float* Bp = B + (size_t)(bn+br)*K + kb;

    {   // prime buffer 0
        float4 a0 = *(const float4*)Ap;
        float4 a1 = *(const float4*)(Ap+4);
        float4 b0 = *(const float4*)Bp;
        #pragma unroll
        for (int j=0;j<4;j++){
            As[0][ka+j][ar]   = (&a0.x)[j];
            As[0][ka+4+j][ar] = (&a1.x)[j];
            Bs[0][kb+j][br]   = (&b0.x)[j];
        }
    }
    __syncthreads();

    ull acc[8][2] = {};
    int buf = 0;
    for (int k0 = 16; ; k0 += 16){
        bool more = (k0 < K);
        float4 na0, na1, nb0;
        if (more){
            na0 = *(const float4*)(Ap + k0);
            na1 = *(const float4*)(Ap + k0 + 4);
            nb0 = *(const float4*)(Bp + k0);
        }
        #pragma unroll
        for (int k=0;k<16;k++){
            float4 av0 = *(const float4*)&As[buf][k][ty<<3];
            float4 av1 = *(const float4*)&As[buf][k][(ty<<3)+4];
            ulonglong2 bv = *(const ulonglong2*)&Bs[buf][k][tx<<2];
            float am[8] = { av0.x,av0.y,av0.z,av0.w, av1.x,av1.y,av1.z,av1.w };
            #pragma unroll
            for (int i=0;i<8;i++){
                ull ai = pack2(am[i], am[i]);
                acc[i][0] = ffma2(ai, bv.x, acc[i][0]);
                acc[i][1] = ffma2(ai, bv.y, acc[i][1]);
            }
        }
        if (!more) break;
        int nb = buf ^ 1;
        #pragma unroll
        for (int j=0;j<4;j++){
            As[nb][ka+j][ar]   = (&na0.x)[j];
            As[nb][ka+4+j][ar] = (&na1.x)[j];
            Bs[nb][kb+j][br]   = (&nb0.x)[j];
        }
        __syncthreads();
        buf = nb;
    }

    int n0 = bn + (tx<<2);
    float bb[4] = {0.f,0.f,0.f,0.f};
    if (bias0){ bb[0]=bias0[n0]; bb[1]=bias0[n0+1]; bb[2]=bias0[n0+2]; bb[3]=bias0[n0+3]; }
    if (bias1){ bb[0]+=bias1[n0]; bb[1]+=bias1[n0+1]; bb[2]+=bias1[n0+2]; bb[3]+=bias1[n0+3]; }
    #pragma unroll
    for (int i=0;i<8;i++){
        int m = bm + (ty<<3) + i;
        float4 v;
        unpack2(acc[i][0], v.x, v.y);
        unpack2(acc[i][1], v.z, v.w);
        v.x += bb[0]; v.y += bb[1]; v.z += bb[2]; v.w += bb[3];
        if (C0){
            float4 c0 = *(const float4*)&C0[(size_t)m*N + n0];
            v.x += c0.x; v.y += c0.y; v.z += c0.z; v.w += c0.w;
        }
        *(float4*)&C[(size_t)m*N + n0] = v;
    }
}

// ---------------- fused recurrence GEMM + LSTM pointwise (gate-permuted, 128x64) ----------------
__global__ __launch_bounds__(256) void k_recfused(int s, int T){
    __shared__ __align__(16) float As[2][16][136];
    __shared__ __align__(16) float Bs[2][16][72];
    int d = blockIdx.z;
    int t = d ? (T-1-s) : s;
    int buf0 = s & 1;
    const float* A  = &g_h2[buf0][d][0][0];   // [NW][128]
    const float* B  = &g_WhhP[d][0][0];       // [512][128]
    const float* C0 = &g_P[d][t][0][0];       // [NW][512]
    int bn = blockIdx.x*64, bm = blockIdx.y*128;
    int tid = threadIdx.x;
    int tx = tid & 15, ty = tid >> 4;
    int ar = tid >> 1, ka = (tid & 1) << 3;
    int br = tid >> 2, kb = (tid & 3) << 2;

    const float* Ap = A + (size_t)(bm+ar)*HHd + ka;
    const float* Bp = B + (size_t)(bn+br)*HHd + kb;

    {
        float4 a0 = *(const float4*)Ap;
        float4 a1 = *(const float4*)(Ap+4);
        float4 b0 = *(const float4*)Bp;
        #pragma unroll
        for (int j=0;j<4;j++){
            As[0][ka+j][ar]   = (&a0.x)[j];
            As[0][ka+4+j][ar] = (&a1.x)[j];
            Bs[0][kb+j][br]   = (&b0.x)[j];
        }
    }
    __syncthreads();

    ull acc[8][2] = {};
    int buf = 0;
    #pragma unroll 2
    for (int k0 = 16; ; k0 += 16){
        bool more = (k0 < HHd);
        float4 na0, na1, nb0;
        if (more){
            na0 = *(const float4*)(Ap + k0);
            na1 = *(const float4*)(Ap + k0 + 4);
            nb0 = *(const float4*)(Bp + k0);
        }
        #pragma unroll
        for (int k=0;k<16;k++){
            float4 av0 = *(const float4*)&As[buf][k][ty<<3];
            float4 av1 = *(const float4*)&As[buf][k][(ty<<3)+4];
            ulonglong2 bv = *(const ulonglong2*)&Bs[buf][k][tx<<2];
            float am[8] = { av0.x,av0.y,av0.z,av0.w, av1.x,av1.y,av1.z,av1.w };
            #pragma unroll
            for (int i=0;i<8;i++){
                ull ai = pack2(am[i], am[i]);
                acc[i][0] = ffma2(ai, bv.x, acc[i][0]);
                acc[i][1] = ffma2(ai, bv.y, acc[i][1]);
            }
        }
        if (!more) break;
        int nb = buf ^ 1;
        #pragma unroll
        for (int j=0;j<4;j++){
            As[nb][ka+j][ar]   = (&na0.x)[j];
            As[nb][ka+4+j][ar] = (&na1.x)[j];
            Bs[nb][kb+j][br]   = (&nb0.x)[j];
        }
        __syncthreads();
        buf = nb;
    }

    int n0 = bn + (tx<<2);
    int j = n0 >> 2;               // columns n0..n0+3 = gates i,f,g,o of hidden unit j
    #pragma unroll
    for (int i=0;i<8;i++){
        int m = bm + (ty<<3) + i;
        float4 p = *(const float4*)&C0[(size_t)m*Gd + n0];
        float gi,gf,gg,go;
        unpack2(acc[i][0], gi, gf);
        unpack2(acc[i][1], gg, go);
        gi += p.x; gf += p.y; gg += p.z; go += p.w;
        float c = sigfast(gf)*g_c[d][m][j] + sigfast(gi)*tanha(gg);
        float h = sigfast(go)*tanha(c);
        g_c[d][m][j] = c;
        g_h2[buf0^1][d][m][j] = h;
        g_out[t][m][d*HHd + j] = h;
    }
}

// ---------------- attention score ----------------
__global__ void k_score(int T, const float* __restrict__ wv){
    int gw = blockIdx.x*8 + (threadIdx.x >> 5);
    int lane = threadIdx.x & 31;
    if (gw >= T*NW) return;
    const float* e = &g_E[0][0][0] + (size_t)gw*Hd;
    float a = 0.f;
    #pragma unroll
    for (int i=0;i<8;i++){
        int g = lane + i*32;
        a += tanha(e[g]) * wv[g];
    }
    #pragma unroll
    for (int o=16;o;o>>=1) a += __shfl_xor_sync(0xffffffffu, a, o);
    if (lane == 0) (&g_score[0][0])[gw] = a;
}

// ---------------- softmax over t + weighted context ----------------
__global__ void k_softctx(int T, int off){
    int w = blockIdx.x, tid = threadIdx.x;    // 256 threads
    __shared__ float sc[TCC];
    if (tid < T) sc[tid] = g_score[tid][w];
    __syncthreads();
    float m = -1e30f;
    for (int t=0;t<T;t++) m = fmaxf(m, sc[t]);
    float den = 0.f, acc = 0.f;
    for (int t=0;t<T;t++){
        float e = expf(sc[t]-m);
        den += e;
        acc += e * g_out[t][w][tid];
    }
    g_wordx[w][off + tid] = acc/den;
}

// ---------------- word-level sequential BiLSTM (single CTA/dir, bf16 weight tail) ----
// 2 blocks (dir), 256 threads, 2 gate-rows/thread (r0=t, r1=t+256, natural layout).
// Per row: 96 weights in regs (48 ull), 32 tail weights in smem as bf16 pairs:
// sW[t*36 + k] (k=0..31) = { lo: bf16(row0[96+k]), hi: bf16(row1[96+k]) }.
// stride 36 u32 = 9 16B-chunks, gcd(9,32)=1 -> conflict-free LDS.128.
__global__ __launch_bounds__(256,1) void k_wordrec(
    const float* __restrict__ Whh, const float* __restrict__ PW, float* __restrict__ wout)
{
    __shared__ __align__(16) uint32_t sW[256*36];   // 36864 B
    __shared__ __align__(16) float sh[128];
    __shared__ __align__(16) float scc[128];
    __shared__ __align__(16) float sg[512];
    int dir = blockIdx.x;
    int t0  = threadIdx.x;
    int r0 = t0, r1 = t0 + 256;
    const float* row0 = Whh + ((size_t)dir*Gd + r0)*HHd;
    const float* row1 = Whh + ((size_t)dir*Gd + r1)*HHd;

    ull wa[48], wb[48];
    {
        const ulonglong2* p0 = (const ulonglong2*)row0;
        const ulonglong2* p1 = (const ulonglong2*)row1;
        #pragma unroll
        for (int i=0;i<24;i++){
            ulonglong2 v0 = p0[i]; wa[2*i] = v0.x; wa[2*i+1] = v0.y;
            ulonglong2 v1 = p1[i]; wb[2*i] = v1.x; wb[2*i+1] = v1.y;
        }
    }
    #pragma unroll
    for (int k=0;k<32;k++)
        sW[t0*36 + k] = bf16rn(row0[96+k]) | (bf16rn(row1[96+k]) << 16);
    if (t0 < 128){ sh[t0] = 0.f; scc[t0] = 0.f; }
    const float* PWd = PW + (size_t)dir*NW*Gd;
    __syncthreads();

    for (int s=0;s<NW;s++){
        int t = dir ? (NW-1-s) : s;
        float pv0 = __ldg(&PWd[(size_t)t*Gd + r0]);
        float pv1 = __ldg(&PWd[(size_t)t*Gd + r1]);
        ull a0=0ull, a1=0ull, a2=0ull, a3=0ull;
        const ulonglong2* hp = (const ulonglong2*)sh;
        #pragma unroll
        for (int q=0;q<24;q++){
            ulonglong2 h2 = hp[q];            // h[4q..4q+3]
            a0 = ffma2(wa[2*q],   h2.x, a0);
            a1 = ffma2(wa[2*q+1], h2.y, a1);
            a2 = ffma2(wb[2*q],   h2.x, a2);
            a3 = ffma2(wb[2*q+1], h2.y, a3);
        }
        #pragma unroll
        for (int q=0;q<8;q++){
            ulonglong2 h2 = hp[24+q];         // h[96+4q..99+4q]
            uint4 pw = *(const uint4*)&sW[t0*36 + q*4];
            ull W0a = pack2(blo(pw.x), blo(pw.y));   // row0, k, k+1
            ull W0b = pack2(blo(pw.z), blo(pw.w));   // row0, k+2, k+3
            ull W1a = pack2(bhi(pw.x), bhi(pw.y));   // row1
            ull W1b = pack2(bhi(pw.z), bhi(pw.w));
            a0 = ffma2(W0a, h2.x, a0);
            a1 = ffma2(W0b, h2.y, a1);
            a2 = ffma2(W1a, h2.x, a2);
            a3 = ffma2(W1b, h2.y, a3);
        }
        sg[r0] = pv0 + f2sum(a0) + f2sum(a1);
        sg[r1] = pv1 + f2sum(a2) + f2sum(a3);
        __syncthreads();
        if (t0 < 128){
            float i_ = sg[t0], f_ = sg[128+t0], g_ = sg[256+t0], o_ = sg[384+t0];
            float c = sigfast(f_)*scc[t0] + sigfast(i_)*tanha(g_);
            float h = sigfast(o_)*tanha(c);
            scc[t0] = c; sh[t0] = h;
            wout[(size_t)t*Hd + dir*HHd + t0] = h;
        }
        __syncthreads();
    }
}

// ---------------- final linear heads + log_softmax ----------------
__global__ void k_head(const float* __restrict__ wout,
                       const float* __restrict__ Wp, const float* __restrict__ bp,
                       const float* __restrict__ Wn, const float* __restrict__ bn_,
                       float* __restrict__ out)
{
    int w = blockIdx.x, tid = threadIdx.x;    // 64 threads
    __shared__ float h[Hd];
    __shared__ float lg[60];
    for (int i=tid;i<Hd;i+=64) h[i] = wout[w*Hd + i];
    __syncthreads();
    if (tid < 47){
        float a = bp[tid];
        const float* r = Wp + (size_t)tid*Hd;
        for (int k=0;k<Hd;k++) a += h[k]*r[k];
        lg[tid] = a;
    } else if (tid < 60){
        int n = tid-47;
        float a = bn_[n];
        const float* r = Wn + (size_t)n*Hd;
        for (int k=0;k<Hd;k++) a += h[k]*r[k];
        lg[tid] = a;
    }
    __syncthreads();
    if (tid < 47){
        float m = -1e30f;
        for (int i=0;i<47;i++) m = fmaxf(m, lg[i]);
        float s = 0.f;
        for (int i=0;i<47;i++) s += expf(lg[i]-m);
        out[(size_t)w*47 + tid] = lg[tid] - m - logf(s);
    } else if (tid < 60){
        float m = -1e30f;
        for (int i=47;i<60;i++) m = fmaxf(m, lg[i]);
        float s = 0.f;
        for (int i=47;i<60;i++) s += expf(lg[i]-m);
        out[(size_t)NW*47 + (size_t)w*13 + (tid-47)] = lg[tid] - m - logf(s);
    }
}

// ---------------- orchestration ----------------
extern "C" void kernel_launch(void* const* d_in, const int* in_sizes, int n_in,
                              void* d_out, int out_size)
{
    const int*   word_seq = (const int*)  d_in[0];
    const int*   syl_seq  = (const int*)  d_in[1];
    const int*   char_seq = (const int*)  d_in[2];
    const int*   feat_seq = (const int*)  d_in[3];
    const float* emb_char = (const float*)d_in[4];
    const float* emb_syl  = (const float*)d_in[5];
    const float* emb_word = (const float*)d_in[6];
    const float* emb_pref = (const float*)d_in[7];
    const float* aW_c = (const float*)d_in[8];
    const float* ab_c = (const float*)d_in[9];
    const float* aw_c = (const float*)d_in[10];
    const float* aW_s = (const float*)d_in[11];
    const float* ab_s = (const float*)d_in[12];
    const float* aw_s = (const float*)d_in[13];
    const float* cWih = (const float*)d_in[14];
    const float* cWhh = (const float*)d_in[15];
    const float* cbih = (const float*)d_in[16];
    const float* cbhh = (const float*)d_in[17];
    const float* sWih = (const float*)d_in[18];
    const float* sWhh = (const float*)d_in[19];
    const float* sbih = (const float*)d_in[20];
    const float* sbhh = (const float*)d_in[21];
    const float* wWih = (const float*)d_in[22];
    const float* wWhh = (const float*)d_in[23];
    const float* wbih = (const float*)d_in[24];
    const float* wbhh = (const float*)d_in[25];
    const float* Wp = (const float*)d_in[26];
    const float* bp = (const float*)d_in[27];
    const float* Wn = (const float*)d_in[28];
    const float* bn = (const float*)d_in[29];
    float* out = (float*)d_out;

    float *pX, *pP, *pE, *pWX, *pPW, *pWout, *pWihP, *pbP, *pOut;
    cudaGetSymbolAddress((void**)&pX,    g_X);
    cudaGetSymbolAddress((void**)&pP,    g_P);
    cudaGetSymbolAddress((void**)&pE,    g_E);
    cudaGetSymbolAddress((void**)&pWX,   g_wordx);
    cudaGetSymbolAddress((void**)&pPW,   g_PW);
    cudaGetSymbolAddress((void**)&pWout, g_wout);
    cudaGetSymbolAddress((void**)&pWihP, g_WihP);
    cudaGetSymbolAddress((void**)&pbP,   g_bP);
    cudaGetSymbolAddress((void**)&pOut,  g_out);

    // ===== char + syl composition phases =====
    for (int phase = 0; phase < 2; phase++){
        int T            = phase == 0 ? TCC      : TSS;
        const int*   ids = phase == 0 ? char_seq : syl_seq;
        const float* emb = phase == 0 ? emb_char : emb_syl;
        const float* Wih = phase == 0 ? cWih : sWih;
        const float* Whh = phase == 0 ? cWhh : sWhh;
        const float* bih = phase == 0 ? cbih : sbih;
        const float* bhh = phase == 0 ? cbhh : sbhh;
        const float* aW  = phase == 0 ? aW_c : aW_s;
        const float* ab  = phase == 0 ? ab_c : ab_s;
        const float* aw  = phase == 0 ? aw_c : aw_s;
        int off          = phase == 0 ? 256 : 512;
        int M            = T * NW;

        k_permW<<<4, 256>>>(Wih, Whh, bih, bhh);
        k_init<<<2048, 256>>>(feat_seq, emb_pref);
        k_gatherX<<<(NW*T*64 + 255)/256, 256>>>(ids, emb, T);

        // input projections, both directions in one launch (permuted layout)
        k_gemm<<<dim3(Gd/64, M/128, 2), 256>>>(
            pX, pWihP, pbP, nullptr, nullptr, pP,
            M, Gd, 64,
            (long)Gd*64, (long)Gd, 0L, (long)TCC*NW*Gd);

        // recurrence: fused GEMM + LSTM update, both directions per launch
        for (int s = 0; s < T; s++)
            k_recfused<<<dim3(Gd/64, NW/128, 2), 256>>>(s, T);

        // attention
        k_gemm<<<dim3(Hd/64, M/128, 1), 256>>>(pOut, aW, ab, nullptr, nullptr, pE,
                                               M, Hd, Hd, 0L, 0L, 0L, 0L);
        k_score<<<(T*NW)/8, 256>>>(T, aw);
        k_softctx<<<NW, 256>>>(T, off);
    }

    // ===== word-level BiLSTM =====
    k_gatherW<<<NW, 256>>>(word_seq, emb_word);
    k_gemm<<<dim3(Gd/64, NW/128, 2), 256>>>(
        pWX, wWih, wbih, wbhh, nullptr, pPW,
        NW, Gd, WXD,
        (long)Gd*WXD, (long)Gd, 0L, (long)NW*Gd);
    k_wordrec<<<2, 256>>>(wWhh, pPW, pWout);

    // ===== heads =====
    k_head<<<NW, 64>>>(pWout, Wp, bp, Wn, bn, out);
}